// round 3
// baseline (speedup 1.0000x reference)
#include <cuda_runtime.h>
#include <cuda_bf16.h>
#include <cstdint>
#include <cstddef>

#define B_DIM 8192
#define HIN   4096
#define HOUT  4096

// scratch: aw[b][kr] = (x @ qa^T)[b,kr] * top_k_weights[b, kr/8]
__device__ __align__(16) float g_aw[B_DIM * 32];

// ================= Stage 1: aw = (x @ qa^T) * tkw =================
// 64 batch rows per block; qa tile reused from smem (kills qa L2 re-reads).
__global__ void __launch_bounds__(256) lora_a_kernel(
    const float* __restrict__ x, const float* __restrict__ tkw, const float* __restrict__ qa)
{
    __shared__ float xs[64][64];   // x tile: 64 rows x 64 k
    __shared__ float qs[64][33];   // qa tile transposed: [k][kr], padded
    const int tid  = threadIdx.x;
    const int lane = tid & 31, w = tid >> 5;
    const int b0   = blockIdx.x * 64;

    float acc[8] = {0.f, 0.f, 0.f, 0.f, 0.f, 0.f, 0.f, 0.f};

    for (int k0 = 0; k0 < HIN; k0 += 64) {
        __syncthreads();
        #pragma unroll
        for (int i = 0; i < 4; i++) {           // x tile: 1024 float4
            int v = tid + i * 256;
            int r = v >> 4, c = (v & 15) << 2;
            *reinterpret_cast<float4*>(&xs[r][c]) =
                *reinterpret_cast<const float4*>(x + (size_t)(b0 + r) * HIN + k0 + c);
        }
        #pragma unroll
        for (int i = 0; i < 2; i++) {           // qa tile: 512 float4, transposed store
            int v = tid + i * 256;
            int kr = v >> 4, c = (v & 15) << 2;
            float4 f = *reinterpret_cast<const float4*>(qa + (size_t)kr * HIN + k0 + c);
            qs[c + 0][kr] = f.x; qs[c + 1][kr] = f.y;
            qs[c + 2][kr] = f.z; qs[c + 3][kr] = f.w;
        }
        __syncthreads();
        #pragma unroll
        for (int kk = 0; kk < 64; kk += 4) {
            float q0 = qs[kk][lane], q1 = qs[kk + 1][lane];
            float q2 = qs[kk + 2][lane], q3 = qs[kk + 3][lane];
            #pragma unroll
            for (int i = 0; i < 8; i++) {
                float4 xv = *reinterpret_cast<const float4*>(&xs[w * 8 + i][kk]);
                acc[i] += xv.x * q0 + xv.y * q1 + xv.z * q2 + xv.w * q3;
            }
        }
    }
    #pragma unroll
    for (int i = 0; i < 8; i++) {
        int b = b0 + w * 8 + i;
        g_aw[b * 32 + lane] = acc[i] * tkw[b * 4 + (lane >> 3)];
    }
}

// ================= Stage 2: fused GEMM (mma.sync bf16 hi/lo split) =================
// CTA tile M=128 x N=256, K chunks of 64 (chunk 64 = LoRA columns).
// 512 threads = 16 warps in 4x4 grid; warp tile 32x64 via m16n8k16.
#define PITCH_B 144                         // 72 bf16 per smem row (ldmatrix conflict-free)
#define XH_OFF  0
#define XL_OFF  (128 * PITCH_B)             // 18432
#define WH_OFF  (2 * 128 * PITCH_B)         // 36864
#define WL_OFF  (WH_OFF + 256 * PITCH_B)    // 73728
#define STAGE_B (WL_OFF + 256 * PITCH_B)    // 110592
#define SMEM_TOTAL (2 * STAGE_B)            // 221184

__device__ __forceinline__ uint32_t smem_u32(const void* p) {
    uint32_t a;
    asm("{ .reg .u64 t; cvta.to.shared.u64 t, %1; cvt.u32.u64 %0, t; }" : "=r"(a) : "l"(p));
    return a;
}

__device__ __forceinline__ void ldm4(uint32_t* r, uint32_t addr) {
    asm volatile("ldmatrix.sync.aligned.m8n8.x4.shared.b16 {%0,%1,%2,%3}, [%4];"
                 : "=r"(r[0]), "=r"(r[1]), "=r"(r[2]), "=r"(r[3]) : "r"(addr));
}

__device__ __forceinline__ void mma16816(float* c, const uint32_t* a, uint32_t b0, uint32_t b1) {
    asm volatile(
        "mma.sync.aligned.m16n8k16.row.col.f32.bf16.bf16.f32 "
        "{%0,%1,%2,%3}, {%4,%5,%6,%7}, {%8,%9}, {%0,%1,%2,%3};"
        : "+f"(c[0]), "+f"(c[1]), "+f"(c[2]), "+f"(c[3])
        : "r"(a[0]), "r"(a[1]), "r"(a[2]), "r"(a[3]), "r"(b0), "r"(b1));
}

// split fp32x4 -> hi/lo bf16x4 into padded smem layout
__device__ __forceinline__ void split_store(char* hi_base, char* lo_base, int row, int c4, float4 f) {
    uint32_t off = (uint32_t)row * PITCH_B + (uint32_t)c4 * 2u;
    __nv_bfloat16 h0 = __float2bfloat16(f.x);
    __nv_bfloat16 h1 = __float2bfloat16(f.y);
    __nv_bfloat16 h2 = __float2bfloat16(f.z);
    __nv_bfloat16 h3 = __float2bfloat16(f.w);
    __nv_bfloat16 l0 = __float2bfloat16(f.x - __bfloat162float(h0));
    __nv_bfloat16 l1 = __float2bfloat16(f.y - __bfloat162float(h1));
    __nv_bfloat16 l2 = __float2bfloat16(f.z - __bfloat162float(h2));
    __nv_bfloat16 l3 = __float2bfloat16(f.w - __bfloat162float(h3));
    uint2 hv, lv;
    hv.x = (uint32_t)__bfloat16_as_ushort(h0) | ((uint32_t)__bfloat16_as_ushort(h1) << 16);
    hv.y = (uint32_t)__bfloat16_as_ushort(h2) | ((uint32_t)__bfloat16_as_ushort(h3) << 16);
    lv.x = (uint32_t)__bfloat16_as_ushort(l0) | ((uint32_t)__bfloat16_as_ushort(l1) << 16);
    lv.y = (uint32_t)__bfloat16_as_ushort(l2) | ((uint32_t)__bfloat16_as_ushort(l3) << 16);
    *reinterpret_cast<uint2*>(hi_base + off) = hv;
    *reinterpret_cast<uint2*>(lo_base + off) = lv;
}

__device__ __forceinline__ void load_chunk(
    char* buf, int ch, int m0, int n0, int tid,
    const float* __restrict__ x, const float* __restrict__ W,
    const float* __restrict__ qb, const float* __restrict__ scaling)
{
    if (ch < 64) {
        const int k0 = ch * 64;
        #pragma unroll
        for (int i = 0; i < 4; i++) {           // x: 128 x 64 fp32
            int v = tid + i * 512;
            int row = v >> 4, c4 = (v & 15) << 2;
            float4 f = *reinterpret_cast<const float4*>(x + (size_t)(m0 + row) * HIN + k0 + c4);
            split_store(buf + XH_OFF, buf + XL_OFF, row, c4, f);
        }
        #pragma unroll 4
        for (int i = 0; i < 8; i++) {           // W: 256 x 64 fp32
            int v = tid + i * 512;
            int row = v >> 4, c4 = (v & 15) << 2;
            float4 f = *reinterpret_cast<const float4*>(W + (size_t)(n0 + row) * HIN + k0 + c4);
            split_store(buf + WH_OFF, buf + WL_OFF, row, c4, f);
        }
    } else {
        // LoRA chunk: x_ext = aw (32 cols, zero-padded to 64), W_ext = scaling*qb
        #pragma unroll
        for (int i = 0; i < 4; i++) {
            int v = tid + i * 512;
            int row = v >> 4, c4 = (v & 15) << 2;
            float4 f = make_float4(0.f, 0.f, 0.f, 0.f);
            if (c4 < 32)
                f = *reinterpret_cast<const float4*>(g_aw + (m0 + row) * 32 + c4);
            split_store(buf + XH_OFF, buf + XL_OFF, row, c4, f);
        }
        #pragma unroll 4
        for (int i = 0; i < 8; i++) {
            int v = tid + i * 512;
            int row = v >> 4, c4 = (v & 15) << 2;
            float4 f = make_float4(0.f, 0.f, 0.f, 0.f);
            if (c4 < 32) {
                int kk = c4 >> 3, rr = c4 & 7;  // kr = kk*8 + rr, 4 consecutive r
                const float* p = qb + ((size_t)kk * HOUT + (n0 + row)) * 8 + rr;
                float sc = scaling[n0 + row];
                f = make_float4(p[0] * sc, p[1] * sc, p[2] * sc, p[3] * sc);
            }
            split_store(buf + WH_OFF, buf + WL_OFF, row, c4, f);
        }
    }
}

__global__ void __launch_bounds__(512, 1) fused_gemm_kernel(
    const float* __restrict__ x, const float* __restrict__ W,
    const float* __restrict__ qb, const float* __restrict__ scaling,
    float* __restrict__ out)
{
    extern __shared__ char smem[];
    const int tid = threadIdx.x;
    const int wid = tid >> 5, lid = tid & 31;
    const int wr = wid >> 2, wc = wid & 3;        // 4x4 warp grid
    const int n0 = blockIdx.x * 256;
    const int m0 = blockIdx.y * 128;
    const uint32_t sbase = smem_u32(smem);
    const int lr = lid & 15;                      // ldmatrix row lane
    const uint32_t lhb = (uint32_t)(lid >> 4) * 16u;  // +8 cols (bf16) = +16 bytes

    float acc[2][8][4];
    #pragma unroll
    for (int t = 0; t < 2; t++)
        #pragma unroll
        for (int j = 0; j < 8; j++)
            #pragma unroll
            for (int e = 0; e < 4; e++) acc[t][j][e] = 0.f;

    load_chunk(smem, 0, m0, n0, tid, x, W, qb, scaling);
    __syncthreads();

    for (int ch = 0; ch < 65; ch++) {
        const int s = ch & 1;
        if (ch < 64)
            load_chunk(smem + (1 - s) * STAGE_B, ch + 1, m0, n0, tid, x, W, qb, scaling);

        const uint32_t st = sbase + s * STAGE_B;
        const uint32_t xh = st + XH_OFF, xl = st + XL_OFF;
        const uint32_t wh = st + WH_OFF, wl = st + WL_OFF;

        #pragma unroll
        for (int ks = 0; ks < 4; ks++) {
            const uint32_t colb = (uint32_t)ks * 32u + lhb;   // k offset in bytes
            uint32_t ah[2][4], al[2][4];
            #pragma unroll
            for (int t = 0; t < 2; t++) {
                uint32_t rowb = (uint32_t)(wr * 32 + t * 16 + lr) * PITCH_B;
                ldm4(ah[t], xh + rowb + colb);
                ldm4(al[t], xl + rowb + colb);
            }
            #pragma unroll
            for (int g = 0; g < 4; g++) {
                uint32_t nrowb = (uint32_t)(wc * 64 + g * 16 + lr) * PITCH_B;
                uint32_t bh[4], bl[4];
                ldm4(bh, wh + nrowb + colb);
                ldm4(bl, wl + nrowb + colb);
                #pragma unroll
                for (int t = 0; t < 2; t++) {
                    #pragma unroll
                    for (int j2 = 0; j2 < 2; j2++) {
                        float* c = acc[t][g * 2 + j2];
                        mma16816(c, ah[t], bh[j2], bh[j2 + 2]);
                        mma16816(c, ah[t], bl[j2], bl[j2 + 2]);
                        mma16816(c, al[t], bh[j2], bh[j2 + 2]);
                    }
                }
            }
        }
        __syncthreads();
    }

    // Epilogue: direct STG of fp32 accumulators (sector-coalesced float2s)
    #pragma unroll
    for (int t = 0; t < 2; t++) {
        int mr = m0 + wr * 32 + t * 16 + (lid >> 2);
        #pragma unroll
        for (int j = 0; j < 8; j++) {
            int col = n0 + wc * 64 + j * 8 + (lid & 3) * 2;
            *reinterpret_cast<float2*>(out + (size_t)mr * HOUT + col) =
                make_float2(acc[t][j][0], acc[t][j][1]);
            *reinterpret_cast<float2*>(out + (size_t)(mr + 8) * HOUT + col) =
                make_float2(acc[t][j][2], acc[t][j][3]);
        }
    }
}

// ================= launch =================
extern "C" void kernel_launch(void* const* d_in, const int* in_sizes, int n_in,
                              void* d_out, int out_size) {
    const float* x       = (const float*)d_in[0];
    const float* tkw     = (const float*)d_in[1];
    const float* W       = (const float*)d_in[2];
    const float* qa      = (const float*)d_in[3];
    const float* qb      = (const float*)d_in[4];
    const float* scaling = (const float*)d_in[5];
    float* out = (float*)d_out;

    lora_a_kernel<<<B_DIM / 64, 256>>>(x, tkw, qa);

    cudaFuncSetAttribute(fused_gemm_kernel,
                         cudaFuncAttributeMaxDynamicSharedMemorySize, SMEM_TOTAL);
    dim3 grid(HOUT / 256, B_DIM / 128);
    fused_gemm_kernel<<<grid, 512, SMEM_TOTAL>>>(x, W, qb, scaling, out);
}

// round 4
// speedup vs baseline: 1.3986x; 1.3986x over previous
#include <cuda_runtime.h>
#include <cuda_bf16.h>
#include <cstdint>
#include <cstddef>

#define B_DIM 8192
#define HIN   4096
#define HOUT  4096
#define KE    4160          // 4096 + 32 LoRA cols + 32 zero pad = 65 chunks of 64

// ---------------- device scratch ----------------
__device__ __align__(16) float g_aw[B_DIM * 32];
__device__ __align__(16) __nv_bfloat16 g_xh[(size_t)B_DIM * KE];
__device__ __align__(16) __nv_bfloat16 g_xl[(size_t)B_DIM * KE];
__device__ __align__(16) __nv_bfloat16 g_wh[(size_t)HOUT * KE];
__device__ __align__(16) __nv_bfloat16 g_wl[(size_t)HOUT * KE];

// ---------------- helpers ----------------
__device__ __forceinline__ uint32_t smem_u32(const void* p) {
    uint32_t a;
    asm("{ .reg .u64 t; cvta.to.shared.u64 t, %1; cvt.u32.u64 %0, t; }" : "=r"(a) : "l"(p));
    return a;
}

__device__ __forceinline__ void split4(float4 f, uint2& hv, uint2& lv) {
    __nv_bfloat16 h0 = __float2bfloat16(f.x);
    __nv_bfloat16 h1 = __float2bfloat16(f.y);
    __nv_bfloat16 h2 = __float2bfloat16(f.z);
    __nv_bfloat16 h3 = __float2bfloat16(f.w);
    __nv_bfloat16 l0 = __float2bfloat16(f.x - __bfloat162float(h0));
    __nv_bfloat16 l1 = __float2bfloat16(f.y - __bfloat162float(h1));
    __nv_bfloat16 l2 = __float2bfloat16(f.z - __bfloat162float(h2));
    __nv_bfloat16 l3 = __float2bfloat16(f.w - __bfloat162float(h3));
    hv.x = (uint32_t)__bfloat16_as_ushort(h0) | ((uint32_t)__bfloat16_as_ushort(h1) << 16);
    hv.y = (uint32_t)__bfloat16_as_ushort(h2) | ((uint32_t)__bfloat16_as_ushort(h3) << 16);
    lv.x = (uint32_t)__bfloat16_as_ushort(l0) | ((uint32_t)__bfloat16_as_ushort(l1) << 16);
    lv.y = (uint32_t)__bfloat16_as_ushort(l2) | ((uint32_t)__bfloat16_as_ushort(l3) << 16);
}

__device__ __forceinline__ void cpa16(uint32_t dst, const void* src) {
    asm volatile("cp.async.cg.shared.global [%0], [%1], 16;" :: "r"(dst), "l"(src));
}

__device__ __forceinline__ void ldm4(uint32_t* r, uint32_t addr) {
    asm volatile("ldmatrix.sync.aligned.m8n8.x4.shared.b16 {%0,%1,%2,%3}, [%4];"
                 : "=r"(r[0]), "=r"(r[1]), "=r"(r[2]), "=r"(r[3]) : "r"(addr));
}

__device__ __forceinline__ void mma16816(float* c, const uint32_t* a, uint32_t b0, uint32_t b1) {
    asm volatile(
        "mma.sync.aligned.m16n8k16.row.col.f32.bf16.bf16.f32 "
        "{%0,%1,%2,%3}, {%4,%5,%6,%7}, {%8,%9}, {%0,%1,%2,%3};"
        : "+f"(c[0]), "+f"(c[1]), "+f"(c[2]), "+f"(c[3])
        : "r"(a[0]), "r"(a[1]), "r"(a[2]), "r"(a[3]), "r"(b0), "r"(b1));
}

// ================= Stage 1: aw = (x @ qa^T) * tkw =================
__global__ void __launch_bounds__(256) lora_a_kernel(
    const float* __restrict__ x, const float* __restrict__ tkw, const float* __restrict__ qa)
{
    __shared__ float xs[64][64];
    __shared__ float qs[64][33];
    const int tid  = threadIdx.x;
    const int lane = tid & 31, w = tid >> 5;
    const int b0   = blockIdx.x * 64;

    float acc[8] = {0.f, 0.f, 0.f, 0.f, 0.f, 0.f, 0.f, 0.f};

    for (int k0 = 0; k0 < HIN; k0 += 64) {
        __syncthreads();
        #pragma unroll
        for (int i = 0; i < 4; i++) {
            int v = tid + i * 256;
            int r = v >> 4, c = (v & 15) << 2;
            *reinterpret_cast<float4*>(&xs[r][c]) =
                *reinterpret_cast<const float4*>(x + (size_t)(b0 + r) * HIN + k0 + c);
        }
        #pragma unroll
        for (int i = 0; i < 2; i++) {
            int v = tid + i * 256;
            int kr = v >> 4, c = (v & 15) << 2;
            float4 f = *reinterpret_cast<const float4*>(qa + (size_t)kr * HIN + k0 + c);
            qs[c + 0][kr] = f.x; qs[c + 1][kr] = f.y;
            qs[c + 2][kr] = f.z; qs[c + 3][kr] = f.w;
        }
        __syncthreads();
        #pragma unroll
        for (int kk = 0; kk < 64; kk += 4) {
            float q0 = qs[kk][lane], q1 = qs[kk + 1][lane];
            float q2 = qs[kk + 2][lane], q3 = qs[kk + 3][lane];
            #pragma unroll
            for (int i = 0; i < 8; i++) {
                float4 xv = *reinterpret_cast<const float4*>(&xs[w * 8 + i][kk]);
                acc[i] += xv.x * q0 + xv.y * q1 + xv.z * q2 + xv.w * q3;
            }
        }
    }
    #pragma unroll
    for (int i = 0; i < 8; i++) {
        int b = b0 + w * 8 + i;
        g_aw[b * 32 + lane] = acc[i] * tkw[b * 4 + (lane >> 3)];
    }
}

// ================= Stage 2a: convert x (+aw, +pad) to bf16 hi/lo planes =================
__global__ void __launch_bounds__(256) cvt_x_kernel(const float* __restrict__ x)
{
    const int b = blockIdx.x, tid = threadIdx.x;
    const size_t rb = (size_t)b * KE;
    uint2 hv, lv;
    #pragma unroll
    for (int i = 0; i < 4; i++) {
        int c4 = (tid + i * 256) << 2;
        float4 f = *reinterpret_cast<const float4*>(x + (size_t)b * HIN + c4);
        split4(f, hv, lv);
        *reinterpret_cast<uint2*>(g_xh + rb + c4) = hv;
        *reinterpret_cast<uint2*>(g_xl + rb + c4) = lv;
    }
    if (tid < 8) {
        int c4 = 4096 + tid * 4;
        float4 f = *reinterpret_cast<const float4*>(g_aw + b * 32 + tid * 4);
        split4(f, hv, lv);
        *reinterpret_cast<uint2*>(g_xh + rb + c4) = hv;
        *reinterpret_cast<uint2*>(g_xl + rb + c4) = lv;
    } else if (tid < 16) {
        int c4 = 4128 + (tid - 8) * 4;
        uint2 z = make_uint2(0u, 0u);
        *reinterpret_cast<uint2*>(g_xh + rb + c4) = z;
        *reinterpret_cast<uint2*>(g_xl + rb + c4) = z;
    }
}

// ================= Stage 2b: convert W (+scaling*qb, +pad) to bf16 hi/lo planes =========
__global__ void __launch_bounds__(256) cvt_w_kernel(
    const float* __restrict__ W, const float* __restrict__ qb, const float* __restrict__ scaling)
{
    const int o = blockIdx.x, tid = threadIdx.x;
    const size_t rb = (size_t)o * KE;
    uint2 hv, lv;
    #pragma unroll
    for (int i = 0; i < 4; i++) {
        int c4 = (tid + i * 256) << 2;
        float4 f = *reinterpret_cast<const float4*>(W + (size_t)o * HIN + c4);
        split4(f, hv, lv);
        *reinterpret_cast<uint2*>(g_wh + rb + c4) = hv;
        *reinterpret_cast<uint2*>(g_wl + rb + c4) = lv;
    }
    if (tid < 8) {
        int c4 = 4096 + tid * 4;
        int kk = tid >> 1, rr = (tid & 1) * 4;       // kr = kk*8 + rr..rr+3
        const float* p = qb + ((size_t)kk * HOUT + o) * 8 + rr;
        float sc = scaling[o];
        float4 f = make_float4(p[0] * sc, p[1] * sc, p[2] * sc, p[3] * sc);
        split4(f, hv, lv);
        *reinterpret_cast<uint2*>(g_wh + rb + c4) = hv;
        *reinterpret_cast<uint2*>(g_wl + rb + c4) = lv;
    } else if (tid < 16) {
        int c4 = 4128 + (tid - 8) * 4;
        uint2 z = make_uint2(0u, 0u);
        *reinterpret_cast<uint2*>(g_wh + rb + c4) = z;
        *reinterpret_cast<uint2*>(g_wl + rb + c4) = z;
    }
}

// ================= Stage 3: GEMM (mma.sync bf16 3-pass, cp.async pipeline) =============
// CTA tile M=128 x N=256, 512 threads (4x4 warp grid, warp tile 32x64).
// SW128-swizzled smem, 2 stages of K=64.
#define XH_OFF 0
#define XL_OFF 16384
#define WH_OFF 32768
#define WL_OFF 65536
#define STAGE_B 98304
#define SMEM_TOTAL (2 * STAGE_B)

__device__ __forceinline__ void issue_stage(uint32_t st, int ch, int m0, int n0, int tid)
{
    const int r = tid >> 3, s = tid & 7;
    const size_t kofs = (size_t)ch * 64 + s * 8;
    const uint32_t segb = (uint32_t)s * 16u;
    #pragma unroll
    for (int j = 0; j < 2; j++) {
        int row = r + 64 * j;
        uint32_t d = (uint32_t)row * 128u + (segb ^ ((uint32_t)(row & 7) << 4));
        const size_t gofs = (size_t)(m0 + row) * KE + kofs;
        cpa16(st + XH_OFF + d, g_xh + gofs);
        cpa16(st + XL_OFF + d, g_xl + gofs);
    }
    #pragma unroll
    for (int j = 0; j < 4; j++) {
        int row = r + 64 * j;
        uint32_t d = (uint32_t)row * 128u + (segb ^ ((uint32_t)(row & 7) << 4));
        const size_t gofs = (size_t)(n0 + row) * KE + kofs;
        cpa16(st + WH_OFF + d, g_wh + gofs);
        cpa16(st + WL_OFF + d, g_wl + gofs);
    }
    asm volatile("cp.async.commit_group;" ::: "memory");
}

__global__ void __launch_bounds__(512, 1) fused_gemm_kernel(float* __restrict__ out)
{
    extern __shared__ char smem[];
    const int tid = threadIdx.x;
    const int wid = tid >> 5, lid = tid & 31;
    const int wr = wid >> 2, wc = wid & 3;
    const int n0 = blockIdx.x * 256;
    const int m0 = blockIdx.y * 128;
    const uint32_t sbase = smem_u32(smem);
    const int lr = lid & 15;
    const uint32_t lhb = (uint32_t)(lid >> 4) * 16u;

    float acc[2][8][4];
    #pragma unroll
    for (int t = 0; t < 2; t++)
        #pragma unroll
        for (int j = 0; j < 8; j++)
            #pragma unroll
            for (int e = 0; e < 4; e++) acc[t][j][e] = 0.f;

    issue_stage(sbase, 0, m0, n0, tid);

    for (int ch = 0; ch < 65; ch++) {
        const int s = ch & 1;
        const uint32_t st = sbase + s * STAGE_B;

        asm volatile("cp.async.wait_group 0;" ::: "memory");
        __syncthreads();
        if (ch < 64)
            issue_stage(sbase + (1 - s) * STAGE_B, ch + 1, m0, n0, tid);

        #pragma unroll
        for (int ks = 0; ks < 4; ks++) {
            const uint32_t colb = (uint32_t)ks * 32u + lhb;
            uint32_t ah[2][4], al[2][4];
            #pragma unroll
            for (int t = 0; t < 2; t++) {
                uint32_t row = (uint32_t)(wr * 32 + t * 16 + lr);
                uint32_t d = row * 128u + (colb ^ ((row & 7u) << 4));
                ldm4(ah[t], st + XH_OFF + d);
                ldm4(al[t], st + XL_OFF + d);
            }
            #pragma unroll
            for (int g = 0; g < 4; g++) {
                uint32_t row = (uint32_t)(wc * 64 + g * 16 + lr);
                uint32_t d = row * 128u + (colb ^ ((row & 7u) << 4));
                uint32_t bh[4], bl[4];
                ldm4(bh, st + WH_OFF + d);
                ldm4(bl, st + WL_OFF + d);
                #pragma unroll
                for (int t = 0; t < 2; t++) {
                    #pragma unroll
                    for (int j2 = 0; j2 < 2; j2++) {
                        float* c = acc[t][g * 2 + j2];
                        mma16816(c, ah[t], bh[j2], bh[j2 + 2]);
                        mma16816(c, ah[t], bl[j2], bl[j2 + 2]);
                        mma16816(c, al[t], bh[j2], bh[j2 + 2]);
                    }
                }
            }
        }
    }

    // Epilogue: direct fp32 STG (float2 sector-coalesced)
    #pragma unroll
    for (int t = 0; t < 2; t++) {
        int mr = m0 + wr * 32 + t * 16 + (lid >> 2);
        #pragma unroll
        for (int j = 0; j < 8; j++) {
            int col = n0 + wc * 64 + j * 8 + (lid & 3) * 2;
            *reinterpret_cast<float2*>(out + (size_t)mr * HOUT + col) =
                make_float2(acc[t][j][0], acc[t][j][1]);
            *reinterpret_cast<float2*>(out + (size_t)(mr + 8) * HOUT + col) =
                make_float2(acc[t][j][2], acc[t][j][3]);
        }
    }
}

// ================= launch =================
extern "C" void kernel_launch(void* const* d_in, const int* in_sizes, int n_in,
                              void* d_out, int out_size) {
    const float* x       = (const float*)d_in[0];
    const float* tkw     = (const float*)d_in[1];
    const float* W       = (const float*)d_in[2];
    const float* qa      = (const float*)d_in[3];
    const float* qb      = (const float*)d_in[4];
    const float* scaling = (const float*)d_in[5];
    float* out = (float*)d_out;

    lora_a_kernel<<<B_DIM / 64, 256>>>(x, tkw, qa);
    cvt_w_kernel<<<HOUT, 256>>>(W, qb, scaling);
    cvt_x_kernel<<<B_DIM, 256>>>(x);

    cudaFuncSetAttribute(fused_gemm_kernel,
                         cudaFuncAttributeMaxDynamicSharedMemorySize, SMEM_TOTAL);
    dim3 grid(HOUT / 256, B_DIM / 128);
    fused_gemm_kernel<<<grid, 512, SMEM_TOTAL>>>(out);
}